// round 1
// baseline (speedup 1.0000x reference)
#include <cuda_runtime.h>
#include <cuda_bf16.h>
#include <math.h>

#define N_NODES 100000
#define N_EDGES 1600000
#define IN_C 64
#define HID_C 64
#define OUT_C 40

// Scratch (allocation-free rule: __device__ globals)
__device__ float g_tmp[(size_t)N_NODES * HID_C];   // GEMM output (also holds 40-wide last layer)
__device__ float g_h[(size_t)N_NODES * HID_C];     // aggregated layer output / next layer input
__device__ float g_dinv[N_NODES];
__device__ int   g_deg[N_NODES];

// ---------------------------------------------------------------------------
// degree / normalization
// ---------------------------------------------------------------------------
__global__ void zero_deg_kernel(int N) {
    int i = blockIdx.x * blockDim.x + threadIdx.x;
    if (i < N) g_deg[i] = 0;
}

__global__ void deg_kernel(const int* __restrict__ dst, int E) {
    int i = blockIdx.x * blockDim.x + threadIdx.x;
    if (i < E) atomicAdd(&g_deg[dst[i]], 1);
}

__global__ void dinv_kernel(int N) {
    int i = blockIdx.x * blockDim.x + threadIdx.x;
    if (i < N) g_dinv[i] = rsqrtf((float)(g_deg[i] + 1));  // +1 self loop; always > 0
}

// ---------------------------------------------------------------------------
// dense transform: Y[r, :] = (relu?)X[r, :] @ W   (W in smem, row per thread)
// ---------------------------------------------------------------------------
template <int IN, int OUT, bool RELU>
__global__ void gemm_kernel(const float* __restrict__ X, const float* __restrict__ W,
                            float* __restrict__ Y, int N) {
    __shared__ float Ws[IN * OUT];
    for (int i = threadIdx.x; i < IN * OUT; i += blockDim.x) Ws[i] = W[i];
    __syncthreads();

    int r = blockIdx.x * blockDim.x + threadIdx.x;
    if (r >= N) return;

    float acc[OUT];
#pragma unroll
    for (int j = 0; j < OUT; j++) acc[j] = 0.f;

    const float4* xr = reinterpret_cast<const float4*>(X + (size_t)r * IN);
#pragma unroll 4
    for (int k4 = 0; k4 < IN / 4; k4++) {
        float4 xv = xr[k4];
        if (RELU) {
            xv.x = fmaxf(xv.x, 0.f); xv.y = fmaxf(xv.y, 0.f);
            xv.z = fmaxf(xv.z, 0.f); xv.w = fmaxf(xv.w, 0.f);
        }
        float xs[4] = {xv.x, xv.y, xv.z, xv.w};
#pragma unroll
        for (int kk = 0; kk < 4; kk++) {
            float x = xs[kk];
            const float4* wr = reinterpret_cast<const float4*>(Ws + (4 * k4 + kk) * OUT);
#pragma unroll
            for (int j = 0; j < OUT / 4; j++) {
                float4 w = wr[j];
                acc[4 * j + 0] += x * w.x;
                acc[4 * j + 1] += x * w.y;
                acc[4 * j + 2] += x * w.z;
                acc[4 * j + 3] += x * w.w;
            }
        }
    }
    float4* yr = reinterpret_cast<float4*>(Y + (size_t)r * OUT);
#pragma unroll
    for (int j = 0; j < OUT / 4; j++)
        yr[j] = make_float4(acc[4 * j], acc[4 * j + 1], acc[4 * j + 2], acc[4 * j + 3]);
}

// ---------------------------------------------------------------------------
// out[i, :] = b + tmp[i, :] * dinv[i]^2  (self-loop + bias init)
// ---------------------------------------------------------------------------
template <int C4>
__global__ void init_kernel(const float* __restrict__ tmp, const float* __restrict__ b,
                            float* __restrict__ out, int N) {
    int idx = blockIdx.x * blockDim.x + threadIdx.x;
    if (idx >= N * C4) return;
    int row = idx / C4;
    int c4  = idx - row * C4;
    float di = g_dinv[row];
    float s = di * di;
    float4 t = reinterpret_cast<const float4*>(tmp)[idx];
    float4 bb = reinterpret_cast<const float4*>(b)[c4];
    float4 o;
    o.x = bb.x + t.x * s; o.y = bb.y + t.y * s;
    o.z = bb.z + t.z * s; o.w = bb.w + t.w * s;
    reinterpret_cast<float4*>(out)[idx] = o;
}

// ---------------------------------------------------------------------------
// edge scatter: out[dst, :] += tmp[src, :] * dinv[src] * dinv[dst]
// one float4 per thread, C4 threads per edge (coalesced gather, vector RED)
// ---------------------------------------------------------------------------
__device__ __forceinline__ void red_add_v4(float* addr, float4 v) {
    asm volatile("red.global.add.v4.f32 [%0], {%1, %2, %3, %4};"
                 :: "l"(addr), "f"(v.x), "f"(v.y), "f"(v.z), "f"(v.w)
                 : "memory");
}

template <int C4>
__global__ void scatter_kernel(const int* __restrict__ src, const int* __restrict__ dst,
                               const float* __restrict__ tmp, float* __restrict__ out, int E) {
    int idx = blockIdx.x * blockDim.x + threadIdx.x;
    int e = idx / C4;
    int c4 = idx - e * C4;
    if (e >= E) return;
    int s = __ldg(src + e);
    int d = __ldg(dst + e);
    float nrm = __ldg(&g_dinv[s]) * __ldg(&g_dinv[d]);
    float4 v = reinterpret_cast<const float4*>(tmp)[(size_t)s * C4 + c4];
    v.x *= nrm; v.y *= nrm; v.z *= nrm; v.w *= nrm;
    red_add_v4(reinterpret_cast<float*>(reinterpret_cast<float4*>(out) + (size_t)d * C4 + c4), v);
}

// ---------------------------------------------------------------------------
// row-wise log_softmax over OUT_C=40
// ---------------------------------------------------------------------------
__global__ void lsm_kernel(const float* __restrict__ h, float* __restrict__ out, int N) {
    int r = blockIdx.x * blockDim.x + threadIdx.x;
    if (r >= N) return;
    float v[OUT_C];
    const float4* hr = reinterpret_cast<const float4*>(h + (size_t)r * OUT_C);
#pragma unroll
    for (int j = 0; j < OUT_C / 4; j++) {
        float4 t = hr[j];
        v[4 * j] = t.x; v[4 * j + 1] = t.y; v[4 * j + 2] = t.z; v[4 * j + 3] = t.w;
    }
    float m = v[0];
#pragma unroll
    for (int j = 1; j < OUT_C; j++) m = fmaxf(m, v[j]);
    float s = 0.f;
#pragma unroll
    for (int j = 0; j < OUT_C; j++) s += __expf(v[j] - m);
    float l = m + logf(s);
    float4* orow = reinterpret_cast<float4*>(out + (size_t)r * OUT_C);
#pragma unroll
    for (int j = 0; j < OUT_C / 4; j++)
        orow[j] = make_float4(v[4 * j] - l, v[4 * j + 1] - l, v[4 * j + 2] - l, v[4 * j + 3] - l);
}

// ---------------------------------------------------------------------------
// launcher
// ---------------------------------------------------------------------------
extern "C" void kernel_launch(void* const* d_in, const int* in_sizes, int n_in,
                              void* d_out, int out_size) {
    const float* x  = (const float*)d_in[0];
    const int*   ei = (const int*)d_in[1];
    const float* W1 = (const float*)d_in[2];
    const float* b1 = (const float*)d_in[3];
    const float* Wh = (const float*)d_in[4];
    const float* bh = (const float*)d_in[5];
    const float* W2 = (const float*)d_in[6];
    const float* b2 = (const float*)d_in[7];
    float* out = (float*)d_out;

    int N = in_sizes[0] / IN_C;
    int E = in_sizes[1] / 2;
    const int* src = ei;
    const int* dst = ei + E;

    float *p_tmp, *p_h;
    cudaGetSymbolAddress((void**)&p_tmp, g_tmp);
    cudaGetSymbolAddress((void**)&p_h, g_h);

    const int T = 256;
    int nb_N   = (N + T - 1) / T;

    // normalization: deg (with self loop) -> dinv
    zero_deg_kernel<<<nb_N, T>>>(N);
    deg_kernel<<<(E + T - 1) / T, T>>>(dst, E);
    dinv_kernel<<<nb_N, T>>>(N);

    // ---- layer 1: x @ W1, aggregate, (relu fused into next gemm) ----
    gemm_kernel<IN_C, HID_C, false><<<nb_N, T>>>(x, W1, p_tmp, N);
    init_kernel<HID_C / 4><<<(N * (HID_C / 4) + T - 1) / T, T>>>(p_tmp, b1, p_h, N);
    scatter_kernel<HID_C / 4><<<((long long)E * (HID_C / 4) + T - 1) / T, T>>>(src, dst, p_tmp, p_h, E);

    // ---- layer 2: relu(h) @ Wh, aggregate ----
    gemm_kernel<HID_C, HID_C, true><<<nb_N, T>>>(p_h, Wh, p_tmp, N);
    init_kernel<HID_C / 4><<<(N * (HID_C / 4) + T - 1) / T, T>>>(p_tmp, bh, p_h, N);
    scatter_kernel<HID_C / 4><<<((long long)E * (HID_C / 4) + T - 1) / T, T>>>(src, dst, p_tmp, p_h, E);

    // ---- layer 3: relu(h) @ W2 (40-wide), aggregate, log_softmax ----
    gemm_kernel<HID_C, OUT_C, true><<<nb_N, T>>>(p_h, W2, p_tmp, N);
    init_kernel<OUT_C / 4><<<(N * (OUT_C / 4) + T - 1) / T, T>>>(p_tmp, b2, p_h, N);
    scatter_kernel<OUT_C / 4><<<((long long)E * (OUT_C / 4) + T - 1) / T, T>>>(src, dst, p_tmp, p_h, E);

    lsm_kernel<<<nb_N, T>>>(p_h, out, N);
}